// round 16
// baseline (speedup 1.0000x reference)
#include <cuda_runtime.h>
#include <cuda_bf16.h>
#include <cstdint>

#define NN 128
#define LL 256
#define CM 256
#define CH 32
#define CZ 128
#define RTOT 8192   // LL*CH

// ---------------- global scratch ----------------
__device__ __align__(16) __nv_bfloat16 g_Xh[(size_t)32768 * 256];  // LN(x) hi
__device__ __align__(16) __nv_bfloat16 g_Xl[(size_t)32768 * 256];  // LN(x) lo
__device__ __align__(16) __nv_bfloat16 g_Wth[64 * 256];   // [o][k]  ([Wa|Wb]^T)
__device__ __align__(16) __nv_bfloat16 g_Wtl[64 * 256];
__device__ __align__(16) __nv_bfloat16 g_Ah[RTOT * NN];   // [r=i*32+h][n]
__device__ __align__(16) __nv_bfloat16 g_Al[RTOT * NN];
__device__ __align__(16) __nv_bfloat16 g_Bh[RTOT * NN];
__device__ __align__(16) __nv_bfloat16 g_Bl[RTOT * NN];
__device__ __align__(16) __nv_bfloat16 g_Woh[CZ * 1024];  // [z][k] (Wo^T)
__device__ __align__(16) __nv_bfloat16 g_Wol[CZ * 1024];
__device__ float g_pm[LL * LL];

// ---------------- helpers ----------------
__device__ __forceinline__ uint32_t smem_u32(const void* p) {
    uint32_t a;
    asm("{ .reg .u64 t; cvta.to.shared.u64 t, %1; cvt.u32.u64 %0, t; }" : "=r"(a) : "l"(p));
    return a;
}
__device__ __forceinline__ void ldsm4(uint32_t* r, uint32_t addr) {
    asm volatile("ldmatrix.sync.aligned.m8n8.x4.shared.b16 {%0,%1,%2,%3}, [%4];"
        : "=r"(r[0]), "=r"(r[1]), "=r"(r[2]), "=r"(r[3]) : "r"(addr));
}
__device__ __forceinline__ void mma_bf16(float* d, const uint32_t* a,
                                         uint32_t b0, uint32_t b1) {
    asm volatile(
        "mma.sync.aligned.m16n8k16.row.col.f32.bf16.bf16.f32 "
        "{%0,%1,%2,%3}, {%4,%5,%6,%7}, {%8,%9}, {%0,%1,%2,%3};"
        : "+f"(d[0]), "+f"(d[1]), "+f"(d[2]), "+f"(d[3])
        : "r"(a[0]), "r"(a[1]), "r"(a[2]), "r"(a[3]), "r"(b0), "r"(b1));
}
#define CP16(dst, src) asm volatile("cp.async.cg.shared.global [%0], [%1], 16;" :: "r"(dst), "l"(src))
#define CP_COMMIT()    asm volatile("cp.async.commit_group;" ::: "memory")
#define CP_WAIT(n)     asm volatile("cp.async.wait_group %0;" :: "n"(n) : "memory")

__device__ __forceinline__ void split1(float x, __nv_bfloat16& h, __nv_bfloat16& l) {
    h = __float2bfloat16(x);
    l = __float2bfloat16(x - __bfloat162float(h));
}

// ---------------------------------------------------------------------------
// ln_prep_kernel: blocks [0,4096) = warp-per-row LayerNorm;
//                 blocks [4096,4480) = prep (pm table, Wo split, Wt split)
// ---------------------------------------------------------------------------
__global__ __launch_bounds__(256) void ln_prep_kernel(
    const float* __restrict__ m, const float* __restrict__ gamma,
    const float* __restrict__ beta, const float* __restrict__ mask,
    const float* __restrict__ Wo,
    const float* __restrict__ Wa, const float* __restrict__ Wb)
{
    if (blockIdx.x < 4096) {
        const int row  = blockIdx.x * 8 + (threadIdx.x >> 5);
        const int lane = threadIdx.x & 31;
        const size_t base = (size_t)row * 256 + lane * 8;

        const float4 v0 = *reinterpret_cast<const float4*>(m + base);
        const float4 v1 = *reinterpret_cast<const float4*>(m + base + 4);
        float x[8] = {v0.x, v0.y, v0.z, v0.w, v1.x, v1.y, v1.z, v1.w};

        float s = 0.f, q = 0.f;
#pragma unroll
        for (int c = 0; c < 8; c++) { s += x[c]; q += x[c] * x[c]; }
#pragma unroll
        for (int o = 16; o > 0; o >>= 1) {
            s += __shfl_xor_sync(0xffffffffu, s, o);
            q += __shfl_xor_sync(0xffffffffu, q, o);
        }
        const float mean = s * (1.f / 256.f);
        const float var  = q * (1.f / 256.f) - mean * mean;
        const float rstd = rsqrtf(var + 1e-5f);

        const float4 g0 = *reinterpret_cast<const float4*>(gamma + lane * 8);
        const float4 g1 = *reinterpret_cast<const float4*>(gamma + lane * 8 + 4);
        const float4 b0 = *reinterpret_cast<const float4*>(beta + lane * 8);
        const float4 b1 = *reinterpret_cast<const float4*>(beta + lane * 8 + 4);
        const float gm[8] = {g0.x, g0.y, g0.z, g0.w, g1.x, g1.y, g1.z, g1.w};
        const float bt[8] = {b0.x, b0.y, b0.z, b0.w, b1.x, b1.y, b1.z, b1.w};

        __nv_bfloat16 hb[8], lb[8];
#pragma unroll
        for (int c = 0; c < 8; c++) {
            const float y = (x[c] - mean) * rstd * gm[c] + bt[c];
            split1(y, hb[c], lb[c]);
        }
        *reinterpret_cast<uint4*>(g_Xh + base) = *reinterpret_cast<const uint4*>(hb);
        *reinterpret_cast<uint4*>(g_Xl + base) = *reinterpret_cast<const uint4*>(lb);
        return;
    }

    const int pb = blockIdx.x - 4096;   // 0..383
    const int t = threadIdx.x;
    if (pb < 256) {
        const int i = pb, j = t;
        float s = 0.f;
        for (int n = 0; n < NN; n++) s += mask[n * LL + i] * mask[n * LL + j];
        g_pm[i * LL + j] = s;
    } else if (pb < 320) {
        const int b = pb - 256;
#pragma unroll
        for (int v = 0; v < 8; v++) {
            const int e = b * 2048 + v * 256 + t;
            const float val = Wo[e];
            const int k = e >> 7, z = e & 127;
            __nv_bfloat16 hi, lo;
            split1(val, hi, lo);
            g_Woh[z * 1024 + k] = hi;
            g_Wol[z * 1024 + k] = lo;
        }
    } else {
        const int idx = (pb - 320) * 256 + t;
        const int o = idx >> 8, k = idx & 255;
        const float val = (o < 32) ? Wa[k * 32 + o] : Wb[k * 32 + (o - 32)];
        __nv_bfloat16 hi, lo;
        split1(val, hi, lo);
        g_Wth[o * 256 + k] = hi;
        g_Wtl[o * 256 + k] = lo;
    }
}

// ---------------------------------------------------------------------------
// proj_kernel (unchanged from R9)
// ---------------------------------------------------------------------------
#define P_XH   0
#define P_XL   67584
#define P_WH   135168
#define P_WL   168960
#define P_MASK 202752
#define P_SMEM 203264

__global__ __launch_bounds__(512) void proj_kernel(
    const float* __restrict__ mask,
    const float* __restrict__ ba, const float* __restrict__ bb)
{
    extern __shared__ char smem[];
    const uint32_t sb = smem_u32(smem);
    const int tid  = threadIdx.x;
    const int lane = tid & 31;
    const int wid  = tid >> 5;
    const int i = blockIdx.x;

#pragma unroll
    for (int v = 0; v < 16; v++) {
        const int idx = v * 512 + tid;
        const int buf = idx >> 12;
        const int rem = idx & 4095;
        const int rown = rem >> 5, q = rem & 31;
        const __nv_bfloat16* src = (buf ? g_Xl : g_Xh) +
            (size_t)(rown * 256 + i) * 256 + q * 8;
        CP16(sb + (buf ? P_XL : P_XH) + rown * 528 + q * 16, src);
    }
#pragma unroll
    for (int v = 0; v < 8; v++) {
        const int idx = v * 512 + tid;
        const int buf = idx >> 11;
        const int rem = idx & 2047;
        const int rowo = rem >> 5, q = rem & 31;
        const __nv_bfloat16* src = (buf ? g_Wtl : g_Wth) + rowo * 256 + q * 8;
        CP16(sb + (buf ? P_WL : P_WH) + rowo * 528 + q * 16, src);
    }
    CP_COMMIT();

    if (tid < 128)
        *reinterpret_cast<float*>(smem + P_MASK + tid * 4) = mask[tid * LL + i];

    CP_WAIT(0);
    __syncthreads();

    const int wm = wid >> 2, wn = wid & 3;
    float acc[2][2][4];
#pragma unroll
    for (int fm = 0; fm < 2; fm++)
#pragma unroll
        for (int fn = 0; fn < 2; fn++)
#pragma unroll
            for (int e = 0; e < 4; e++) acc[fm][fn][e] = 0.f;

    const uint32_t rofs = (uint32_t)((lane & 15) * 528 + (lane >> 4) * 16);
    const uint32_t aXh = sb + P_XH + wm * 32 * 528 + rofs;
    const uint32_t aXl = sb + P_XL + wm * 32 * 528 + rofs;
    const uint32_t aWh = sb + P_WH + wn * 16 * 528 + rofs;
    const uint32_t aWl = sb + P_WL + wn * 16 * 528 + rofs;

#pragma unroll
    for (int ks = 0; ks < 16; ks++) {
        uint32_t X_h[2][4], X_l[2][4], W_h[4], W_l[4];
        ldsm4(X_h[0], aXh + ks * 32);
        ldsm4(X_h[1], aXh + 16 * 528 + ks * 32);
        ldsm4(X_l[0], aXl + ks * 32);
        ldsm4(X_l[1], aXl + 16 * 528 + ks * 32);
        ldsm4(W_h, aWh + ks * 32);
        ldsm4(W_l, aWl + ks * 32);
#pragma unroll
        for (int fm = 0; fm < 2; fm++)
#pragma unroll
            for (int fn = 0; fn < 2; fn++)
                mma_bf16(acc[fm][fn], X_h[fm], W_h[fn], W_h[fn + 2]);
#pragma unroll
        for (int fm = 0; fm < 2; fm++)
#pragma unroll
            for (int fn = 0; fn < 2; fn++)
                mma_bf16(acc[fm][fn], X_h[fm], W_l[fn], W_l[fn + 2]);
#pragma unroll
        for (int fm = 0; fm < 2; fm++)
#pragma unroll
            for (int fn = 0; fn < 2; fn++)
                mma_bf16(acc[fm][fn], X_l[fm], W_h[fn], W_h[fn + 2]);
    }

    __syncthreads();

    float* sOut = reinterpret_cast<float*>(smem);
    const float* sMask = reinterpret_cast<const float*>(smem + P_MASK);
#pragma unroll
    for (int fm = 0; fm < 2; fm++)
#pragma unroll
        for (int fn = 0; fn < 2; fn++)
#pragma unroll
            for (int e = 0; e < 4; e++) {
                const int n_loc = wm * 32 + fm * 16 + (lane >> 2) + (e >> 1) * 8;
                const int o     = wn * 16 + fn * 8 + (lane & 3) * 2 + (e & 1);
                const float bias = (o < 32) ? ba[o] : bb[o - 32];
                sOut[o * 132 + n_loc] = (acc[fm][fn][e] + bias) * sMask[n_loc];
            }
    __syncthreads();

    {
        const int o  = tid >> 3;
        const int n0 = (tid & 7) * 16;
        __nv_bfloat16 hb[16], lb[16];
#pragma unroll
        for (int c = 0; c < 16; c++)
            split1(sOut[o * 132 + n0 + c], hb[c], lb[c]);
        __nv_bfloat16* dh = ((o < 32) ? g_Ah : g_Bh) + (size_t)(i * 32 + (o & 31)) * 128 + n0;
        __nv_bfloat16* dl = ((o < 32) ? g_Al : g_Bl) + (size_t)(i * 32 + (o & 31)) * 128 + n0;
        reinterpret_cast<uint4*>(dh)[0] = reinterpret_cast<const uint4*>(hb)[0];
        reinterpret_cast<uint4*>(dh)[1] = reinterpret_cast<const uint4*>(hb)[1];
        reinterpret_cast<uint4*>(dl)[0] = reinterpret_cast<const uint4*>(lb)[0];
        reinterpret_cast<uint4*>(dl)[1] = reinterpret_cast<const uint4*>(lb)[1];
    }
}

// ---------------------------------------------------------------------------
// Fused kernel, 256x128 tile (32 pairs).
// Phase A: as R13, MMAs product-major (no back-to-back RAW on accumulators).
// Phase B: warp = (wn2 = wid&7 -> 16 z, kc = wid>>3 -> 2-way k-split of each
//   64-k chunk). Slice/chunk/warp = 16z x 32k hi+lo = 2KB, double buffered,
//   pitch 80B (conflict-free ldsm, no XOR swizzle). 24 MMAs between CP_WAITs.
//   2-way k-split reduction (1 round).
// SMEM: phase A [0,208896) as before.
//   phase B stages [0, 81920): wid*2560 + st*40960 (hi +0, lo +1280)
//   O  [81920, 214016) (hi 32x2064, lo 32x2064), pm [214016, 214144)
//   red reuses [0, 16384) after post-loop barrier.
// ---------------------------------------------------------------------------
#define F_AH   0
#define F_AL   69632
#define F_BH   139264
#define F_BL   174080
#define OFFO   81920
#define OFFOL  (OFFO + 66048)
#define OFFPM  214016
#define F_SMEM 214144

__global__ __launch_bounds__(512) void fused_kernel(
    const float* __restrict__ bo, float* __restrict__ out)
{
    extern __shared__ char smem[];
    const uint32_t sb = smem_u32(smem);
    const int tid  = threadIdx.x;
    const int lane = tid & 31;
    const int wid  = tid >> 5;
    const int bm = blockIdx.y, bn = blockIdx.x;   // bm 0..31, bn 0..63
    const int i0 = bm * 8, j0 = bn * 4;

    // ======================= Phase A ===============================
#pragma unroll
    for (int kh = 0; kh < 2; kh++) {
#pragma unroll
        for (int v = 0; v < 12; v++) {
            const int idx = v * 512 + tid;
            if (idx < 4096) {
                const int buf = idx >> 11;
                const int rem = idx & 2047;
                const int row = rem >> 3, q = rem & 7;
                const __nv_bfloat16* src = (buf ? g_Al : g_Ah) +
                    (size_t)(bm * 256 + row) * 128 + kh * 64 + q * 8;
                CP16(sb + (buf ? F_AL : F_AH) + row * 272 + kh * 128 + q * 16, src);
            } else {
                const int r2  = idx - 4096;
                const int buf = r2 >> 10;
                const int rem = r2 & 1023;
                const int row = rem >> 3, q = rem & 7;
                const __nv_bfloat16* src = (buf ? g_Bl : g_Bh) +
                    (size_t)(bn * 128 + row) * 128 + kh * 64 + q * 8;
                CP16(sb + (buf ? F_BL : F_BH) + row * 272 + kh * 128 + q * 16, src);
            }
        }
        CP_COMMIT();
    }

    const int wm = wid >> 1, wn = wid & 1;
    float acc[2][8][4];
#pragma unroll
    for (int fm = 0; fm < 2; fm++)
#pragma unroll
        for (int fn = 0; fn < 8; fn++)
#pragma unroll
            for (int e = 0; e < 4; e++) acc[fm][fn][e] = 0.f;

    const uint32_t rofsA = (uint32_t)((lane & 15) * 272 + (lane >> 4) * 16);
    const uint32_t aAh = sb + F_AH + wm * 32 * 272 + rofsA;
    const uint32_t aAl = sb + F_AL + wm * 32 * 272 + rofsA;
    const uint32_t aBh = sb + F_BH + wn * 64 * 272 + rofsA;
    const uint32_t aBl = sb + F_BL + wn * 64 * 272 + rofsA;

    CP_WAIT(1);
    __syncthreads();

#pragma unroll
    for (int ks = 0; ks < 8; ks++) {
        if (ks == 4) { CP_WAIT(0); __syncthreads(); }
        uint32_t A_h[2][4], A_l[2][4];
        ldsm4(A_h[0], aAh + ks * 32);
        ldsm4(A_h[1], aAh + 16 * 272 + ks * 32);
        ldsm4(A_l[0], aAl + ks * 32);
        ldsm4(A_l[1], aAl + 16 * 272 + ks * 32);
#pragma unroll
        for (int bh2 = 0; bh2 < 2; bh2++) {
            uint32_t B_h[2][4], B_l[2][4];
            const uint32_t bo0 = (uint32_t)(bh2 * 32 * 272 + ks * 32);
            ldsm4(B_h[0], aBh + bo0);
            ldsm4(B_h[1], aBh + 16 * 272 + bo0);
            ldsm4(B_l[0], aBl + bo0);
            ldsm4(B_l[1], aBl + 16 * 272 + bo0);
            // product-major: hh pass, hl pass, lh pass (per-acc order preserved)
#pragma unroll
            for (int fm = 0; fm < 2; fm++)
#pragma unroll
                for (int fl = 0; fl < 4; fl++)
                    mma_bf16(acc[fm][bh2 * 4 + fl], A_h[fm],
                             B_h[fl >> 1][fl & 1], B_h[fl >> 1][(fl & 1) + 2]);
#pragma unroll
            for (int fm = 0; fm < 2; fm++)
#pragma unroll
                for (int fl = 0; fl < 4; fl++)
                    mma_bf16(acc[fm][bh2 * 4 + fl], A_h[fm],
                             B_l[fl >> 1][fl & 1], B_l[fl >> 1][(fl & 1) + 2]);
#pragma unroll
            for (int fm = 0; fm < 2; fm++)
#pragma unroll
                for (int fl = 0; fl < 4; fl++)
                    mma_bf16(acc[fm][bh2 * 4 + fl], A_l[fm],
                             B_h[fl >> 1][fl & 1], B_h[fl >> 1][(fl & 1) + 2]);
        }
    }

    __syncthreads();   // all A/B smem reads done; stage region reusable

    // ---- hoisted Wo streaming state (wn2 = 16 z, kc = 2-way k-split) ----
    const int wn2 = wid & 7;
    const int kc  = wid >> 3;
    const uint32_t wstage0 = sb + wid * 2560;
    const int rv = lane >> 1, hv = lane & 1;   // rv 0..15 (z row), hv 0..1 (16k half)
    const __nv_bfloat16* wsrcH = g_Woh + (size_t)(wn2 * 16 + rv) * 1024 + kc * 32 + hv * 16;
    const __nv_bfloat16* wsrcL = g_Wol + (size_t)(wn2 * 16 + rv) * 1024 + kc * 32 + hv * 16;
    const uint32_t dofs = (uint32_t)(rv * 80 + hv * 32);

    // prologue: chunks 0 (stage 0) and 1 (stage 1)
#pragma unroll
    for (int pre = 0; pre < 2; pre++) {
        const uint32_t stb = wstage0 + pre * 40960;
        CP16(stb + dofs, wsrcH);
        CP16(stb + dofs + 16, wsrcH + 8);
        CP16(stb + 1280 + dofs, wsrcL);
        CP16(stb + 1280 + dofs + 16, wsrcL + 8);
        CP_COMMIT();
        wsrcH += 64; wsrcL += 64;
    }

    // ---- O spill: pair p = wm*4 + wn*2 + (fn>>2), k = c*32 + d ----
#pragma unroll
    for (int fm = 0; fm < 2; fm++)
#pragma unroll
        for (int fn = 0; fn < 8; fn++) {
            const int p = wm * 4 + wn * 2 + (fn >> 2);
            char* oh = smem + OFFO  + p * 2064;
            char* ol = smem + OFFOL + p * 2064;
#pragma unroll
            for (int half = 0; half < 2; half++) {
                const int c = fm * 16 + (lane >> 2) + half * 8;
                const int d = (fn & 3) * 8 + (lane & 3) * 2;
                const int k = c * 32 + d;
                __nv_bfloat162 h2, l2;
                split1(acc[fm][fn][half * 2 + 0], h2.x, l2.x);
                split1(acc[fm][fn][half * 2 + 1], h2.y, l2.y);
                *reinterpret_cast<__nv_bfloat162*>(oh + 2 * k) = h2;
                *reinterpret_cast<__nv_bfloat162*>(ol + 2 * k) = l2;
            }
        }
    if (tid < 32) {
        const int ii = i0 + (tid >> 2), jj = j0 + (tid & 3);
        *reinterpret_cast<float*>(smem + OFFPM + tid * 4) =
            1.f / (g_pm[ii * LL + jj] + 1e-8f);
    }
    __syncthreads();   // O + pm visible to all warps

    // ======================= Phase B: barrier-free ==========================
    float acc2[2][2][4];
#pragma unroll
    for (int fm = 0; fm < 2; fm++)
#pragma unroll
        for (int fn = 0; fn < 2; fn++)
#pragma unroll
            for (int e = 0; e < 4; e++) acc2[fm][fn][e] = 0.f;

    const uint32_t aOh = sb + OFFO + (uint32_t)((lane & 15) * 2064 + (lane >> 4) * 16);
    const uint32_t aOl = aOh + 66048;
    const int rB  = lane & 15;
    const int cbB = lane >> 4;
    // B frag addr (within warp stage buf): row rB, quad = ks2*2 + cbB, pitch 80
    const uint32_t bofs0 = (uint32_t)(rB * 80 + cbB * 16);          // ks2 = 0
    const uint32_t bofs1 = bofs0 + 32;                              // ks2 = 1

#pragma unroll
    for (int ck = 0; ck < 16; ck++) {
        const int pp = ck & 1;
        if (ck == 15) CP_WAIT(0); else CP_WAIT(1);
        __syncwarp();

        const uint32_t wb = wstage0 + pp * 40960;
        uint32_t Bh[2][4], Bl[2][4];
        ldsm4(Bh[0], wb + bofs0);
        ldsm4(Bh[1], wb + bofs1);
        ldsm4(Bl[0], wb + 1280 + bofs0);
        ldsm4(Bl[1], wb + 1280 + bofs1);

        if (ck + 2 < 16) {   // refill stage pp for chunk ck+2 (B regs captured)
            CP16(wb + dofs, wsrcH);
            CP16(wb + dofs + 16, wsrcH + 8);
            CP16(wb + 1280 + dofs, wsrcL);
            CP16(wb + 1280 + dofs + 16, wsrcL + 8);
            CP_COMMIT();
            wsrcH += 64; wsrcL += 64;
        }

#pragma unroll
        for (int ks2 = 0; ks2 < 2; ks2++) {
            const uint32_t ao = (uint32_t)(ck * 128 + kc * 64 + ks2 * 32);
            uint32_t AH[2][4], AL[2][4];
            ldsm4(AH[0], aOh + ao);
            ldsm4(AH[1], aOh + 16 * 2064 + ao);
            ldsm4(AL[0], aOl + ao);
            ldsm4(AL[1], aOl + 16 * 2064 + ao);
            // product-major passes
#pragma unroll
            for (int fm = 0; fm < 2; fm++)
#pragma unroll
                for (int fn = 0; fn < 2; fn++)
                    mma_bf16(acc2[fm][fn], AH[fm], Bh[ks2][fn], Bh[ks2][fn + 2]);
#pragma unroll
            for (int fm = 0; fm < 2; fm++)
#pragma unroll
                for (int fn = 0; fn < 2; fn++)
                    mma_bf16(acc2[fm][fn], AH[fm], Bl[ks2][fn], Bl[ks2][fn + 2]);
#pragma unroll
            for (int fm = 0; fm < 2; fm++)
#pragma unroll
                for (int fn = 0; fn < 2; fn++)
                    mma_bf16(acc2[fm][fn], AL[fm], Bh[ks2][fn], Bh[ks2][fn + 2]);
        }
    }

    // all warps finish reading stage buffers before reduction reuses them
    __syncthreads();

    // ---- 2-way k-split reduction via smem [0, 16384) ----
    float* red = reinterpret_cast<float*>(smem);
    if (kc == 1) {
#pragma unroll
        for (int fm = 0; fm < 2; fm++)
#pragma unroll
            for (int fn = 0; fn < 2; fn++)
#pragma unroll
                for (int e = 0; e < 4; e++) {
                    const int p  = fm * 16 + (lane >> 2) + (e >> 1) * 8;
                    const int zl = fn * 8 + (lane & 3) * 2 + (e & 1);
                    red[wn2 * 512 + p * 16 + zl] = acc2[fm][fn][e];
                }
    }
    __syncthreads();
    if (kc == 0) {
        const float* pmv = reinterpret_cast<const float*>(smem + OFFPM);
#pragma unroll
        for (int fm = 0; fm < 2; fm++)
#pragma unroll
            for (int fn = 0; fn < 2; fn++)
#pragma unroll
                for (int e = 0; e < 4; e++) {
                    const int p  = fm * 16 + (lane >> 2) + (e >> 1) * 8;
                    const int zl = fn * 8 + (lane & 3) * 2 + (e & 1);
                    acc2[fm][fn][e] += red[wn2 * 512 + p * 16 + zl];
                }
#pragma unroll
        for (int fm = 0; fm < 2; fm++)
#pragma unroll
            for (int fn = 0; fn < 2; fn++)
#pragma unroll
                for (int prow = 0; prow < 2; prow++) {
                    const int p  = fm * 16 + (lane >> 2) + prow * 8;
                    const int ii = i0 + (p >> 2), jj = j0 + (p & 3);
                    const float inv = pmv[p];
                    const int z = wn2 * 16 + fn * 8 + (lane & 3) * 2;
                    float2 res;
                    res.x = acc2[fm][fn][prow * 2 + 0] * inv + bo[z];
                    res.y = acc2[fm][fn][prow * 2 + 1] * inv + bo[z + 1];
                    *reinterpret_cast<float2*>(out + (size_t)(ii * LL + jj) * CZ + z) = res;
                }
    }
}

// ---------------------------------------------------------------------------
extern "C" void kernel_launch(void* const* d_in, const int* in_sizes, int n_in,
                              void* d_out, int out_size)
{
    const float* m     = (const float*)d_in[0];
    const float* mask  = (const float*)d_in[1];
    const float* gamma = (const float*)d_in[2];
    const float* beta  = (const float*)d_in[3];
    const float* Wa    = (const float*)d_in[4];
    const float* ba    = (const float*)d_in[5];
    const float* Wb    = (const float*)d_in[6];
    const float* bb    = (const float*)d_in[7];
    const float* Wo    = (const float*)d_in[8];
    const float* bo    = (const float*)d_in[9];
    float* out = (float*)d_out;

    cudaFuncSetAttribute(proj_kernel,  cudaFuncAttributeMaxDynamicSharedMemorySize, P_SMEM);
    cudaFuncSetAttribute(fused_kernel, cudaFuncAttributeMaxDynamicSharedMemorySize, F_SMEM);

    ln_prep_kernel<<<4480, 256>>>(m, gamma, beta, mask, Wo, Wa, Wb);
    proj_kernel<<<256, 512, P_SMEM>>>(mask, ba, bb);
    fused_kernel<<<dim3(64, 32), 512, F_SMEM>>>(bo, out);
}

// round 17
// speedup vs baseline: 1.0389x; 1.0389x over previous
#include <cuda_runtime.h>
#include <cuda_bf16.h>
#include <cstdint>

#define NN 128
#define LL 256
#define CM 256
#define CH 32
#define CZ 128
#define RTOT 8192   // LL*CH

// ---------------- global scratch ----------------
__device__ __align__(16) __nv_bfloat16 g_Wth[64 * 256];   // [o][k]  ([Wa|Wb]^T)
__device__ __align__(16) __nv_bfloat16 g_Wtl[64 * 256];
__device__ __align__(16) __nv_bfloat16 g_Ah[RTOT * NN];   // [r=i*32+h][n]
__device__ __align__(16) __nv_bfloat16 g_Al[RTOT * NN];
__device__ __align__(16) __nv_bfloat16 g_Bh[RTOT * NN];
__device__ __align__(16) __nv_bfloat16 g_Bl[RTOT * NN];
__device__ __align__(16) __nv_bfloat16 g_Woh[CZ * 1024];  // [z][k] (Wo^T)
__device__ __align__(16) __nv_bfloat16 g_Wol[CZ * 1024];
__device__ float g_pm[LL * LL];

// ---------------- helpers ----------------
__device__ __forceinline__ uint32_t smem_u32(const void* p) {
    uint32_t a;
    asm("{ .reg .u64 t; cvta.to.shared.u64 t, %1; cvt.u32.u64 %0, t; }" : "=r"(a) : "l"(p));
    return a;
}
__device__ __forceinline__ void ldsm4(uint32_t* r, uint32_t addr) {
    asm volatile("ldmatrix.sync.aligned.m8n8.x4.shared.b16 {%0,%1,%2,%3}, [%4];"
        : "=r"(r[0]), "=r"(r[1]), "=r"(r[2]), "=r"(r[3]) : "r"(addr));
}
__device__ __forceinline__ void mma_bf16(float* d, const uint32_t* a,
                                         uint32_t b0, uint32_t b1) {
    asm volatile(
        "mma.sync.aligned.m16n8k16.row.col.f32.bf16.bf16.f32 "
        "{%0,%1,%2,%3}, {%4,%5,%6,%7}, {%8,%9}, {%0,%1,%2,%3};"
        : "+f"(d[0]), "+f"(d[1]), "+f"(d[2]), "+f"(d[3])
        : "r"(a[0]), "r"(a[1]), "r"(a[2]), "r"(a[3]), "r"(b0), "r"(b1));
}
#define CP16(dst, src) asm volatile("cp.async.cg.shared.global [%0], [%1], 16;" :: "r"(dst), "l"(src))
#define CP_COMMIT()    asm volatile("cp.async.commit_group;" ::: "memory")
#define CP_WAIT(n)     asm volatile("cp.async.wait_group %0;" :: "n"(n) : "memory")

__device__ __forceinline__ void split1(float x, __nv_bfloat16& h, __nv_bfloat16& l) {
    h = __float2bfloat16(x);
    l = __float2bfloat16(x - __bfloat162float(h));
}

// ---------------------------------------------------------------------------
// prep_kernel: pair-mask table + Wo^T bf16 split + [Wa|Wb]^T bf16 split
// ---------------------------------------------------------------------------
__global__ __launch_bounds__(256) void prep_kernel(
    const float* __restrict__ mask, const float* __restrict__ Wo,
    const float* __restrict__ Wa, const float* __restrict__ Wb)
{
    const int t = threadIdx.x;
    if (blockIdx.x < 256) {
        const int i = blockIdx.x, j = t;
        float s = 0.f;
        for (int n = 0; n < NN; n++) s += mask[n * LL + i] * mask[n * LL + j];
        g_pm[i * LL + j] = s;
    } else if (blockIdx.x < 320) {
        const int b = blockIdx.x - 256;
#pragma unroll
        for (int v = 0; v < 8; v++) {
            const int e = b * 2048 + v * 256 + t;
            const float val = Wo[e];
            const int k = e >> 7, z = e & 127;
            __nv_bfloat16 hi, lo;
            split1(val, hi, lo);
            g_Woh[z * 1024 + k] = hi;
            g_Wol[z * 1024 + k] = lo;
        }
    } else {
        const int idx = (blockIdx.x - 320) * 256 + t;
        const int o = idx >> 8, k = idx & 255;
        const float val = (o < 32) ? Wa[k * 32 + o] : Wb[k * 32 + (o - 32)];
        __nv_bfloat16 hi, lo;
        split1(val, hi, lo);
        g_Wth[o * 256 + k] = hi;
        g_Wtl[o * 256 + k] = lo;
    }
}

// ---------------------------------------------------------------------------
// proj_kernel with FUSED LayerNorm: CTA = one i. Warp w LNs rows n = w*8..w*8+7
// of m directly into the X smem tiles (bf16 hi/lo, ldsm layout), overlapped
// with the W-tile cp.asyncs. Then the proven bf16-split mma + epilogue.
// ---------------------------------------------------------------------------
#define P_XH   0
#define P_XL   67584
#define P_WH   135168
#define P_WL   168960
#define P_MASK 202752
#define P_SMEM 203264

__global__ __launch_bounds__(512) void proj_kernel(
    const float* __restrict__ m, const float* __restrict__ gamma,
    const float* __restrict__ beta, const float* __restrict__ mask,
    const float* __restrict__ ba, const float* __restrict__ bb)
{
    extern __shared__ char smem[];
    const uint32_t sb = smem_u32(smem);
    const int tid  = threadIdx.x;
    const int lane = tid & 31;
    const int wid  = tid >> 5;
    const int i = blockIdx.x;

    // W tiles via cp.async first (overlaps the LN LDG work below)
#pragma unroll
    for (int v = 0; v < 8; v++) {
        const int idx = v * 512 + tid;
        const int buf = idx >> 11;
        const int rem = idx & 2047;
        const int rowo = rem >> 5, q = rem & 31;
        const __nv_bfloat16* src = (buf ? g_Wtl : g_Wth) + rowo * 256 + q * 8;
        CP16(sb + (buf ? P_WL : P_WH) + rowo * 528 + q * 16, src);
    }
    CP_COMMIT();

    // ---- fused LayerNorm: warp w -> rows n = w*8 .. w*8+7 ----
    {
        const float4 g0 = *reinterpret_cast<const float4*>(gamma + lane * 8);
        const float4 g1 = *reinterpret_cast<const float4*>(gamma + lane * 8 + 4);
        const float4 b0 = *reinterpret_cast<const float4*>(beta + lane * 8);
        const float4 b1 = *reinterpret_cast<const float4*>(beta + lane * 8 + 4);
        const float gm[8] = {g0.x, g0.y, g0.z, g0.w, g1.x, g1.y, g1.z, g1.w};
        const float bt[8] = {b0.x, b0.y, b0.z, b0.w, b1.x, b1.y, b1.z, b1.w};

#pragma unroll
        for (int r = 0; r < 8; r++) {
            const int n = wid * 8 + r;
            const size_t base = ((size_t)(n * LL + i)) * CM + lane * 8;
            const float4 v0 = *reinterpret_cast<const float4*>(m + base);
            const float4 v1 = *reinterpret_cast<const float4*>(m + base + 4);
            float x[8] = {v0.x, v0.y, v0.z, v0.w, v1.x, v1.y, v1.z, v1.w};

            float s = 0.f, q = 0.f;
#pragma unroll
            for (int c = 0; c < 8; c++) { s += x[c]; q += x[c] * x[c]; }
#pragma unroll
            for (int o = 16; o > 0; o >>= 1) {
                s += __shfl_xor_sync(0xffffffffu, s, o);
                q += __shfl_xor_sync(0xffffffffu, q, o);
            }
            const float mean = s * (1.f / 256.f);
            const float var  = q * (1.f / 256.f) - mean * mean;
            const float rstd = rsqrtf(var + 1e-5f);

            __nv_bfloat16 hb[8], lb[8];
#pragma unroll
            for (int c = 0; c < 8; c++) {
                const float y = (x[c] - mean) * rstd * gm[c] + bt[c];
                split1(y, hb[c], lb[c]);
            }
            *reinterpret_cast<uint4*>(smem + P_XH + n * 528 + lane * 16) =
                *reinterpret_cast<const uint4*>(hb);
            *reinterpret_cast<uint4*>(smem + P_XL + n * 528 + lane * 16) =
                *reinterpret_cast<const uint4*>(lb);
        }
    }

    if (tid < 128)
        *reinterpret_cast<float*>(smem + P_MASK + tid * 4) = mask[tid * LL + i];

    CP_WAIT(0);
    __syncthreads();

    const int wm = wid >> 2, wn = wid & 3;
    float acc[2][2][4];
#pragma unroll
    for (int fm = 0; fm < 2; fm++)
#pragma unroll
        for (int fn = 0; fn < 2; fn++)
#pragma unroll
            for (int e = 0; e < 4; e++) acc[fm][fn][e] = 0.f;

    const uint32_t rofs = (uint32_t)((lane & 15) * 528 + (lane >> 4) * 16);
    const uint32_t aXh = sb + P_XH + wm * 32 * 528 + rofs;
    const uint32_t aXl = sb + P_XL + wm * 32 * 528 + rofs;
    const uint32_t aWh = sb + P_WH + wn * 16 * 528 + rofs;
    const uint32_t aWl = sb + P_WL + wn * 16 * 528 + rofs;

#pragma unroll
    for (int ks = 0; ks < 16; ks++) {
        uint32_t X_h[2][4], X_l[2][4], W_h[4], W_l[4];
        ldsm4(X_h[0], aXh + ks * 32);
        ldsm4(X_h[1], aXh + 16 * 528 + ks * 32);
        ldsm4(X_l[0], aXl + ks * 32);
        ldsm4(X_l[1], aXl + 16 * 528 + ks * 32);
        ldsm4(W_h, aWh + ks * 32);
        ldsm4(W_l, aWl + ks * 32);
#pragma unroll
        for (int fm = 0; fm < 2; fm++)
#pragma unroll
            for (int fn = 0; fn < 2; fn++) {
                const uint32_t bh0 = W_h[fn], bh1 = W_h[fn + 2];
                const uint32_t bl0 = W_l[fn], bl1 = W_l[fn + 2];
                mma_bf16(acc[fm][fn], X_h[fm], bh0, bh1);
                mma_bf16(acc[fm][fn], X_h[fm], bl0, bl1);
                mma_bf16(acc[fm][fn], X_l[fm], bh0, bh1);
            }
    }

    __syncthreads();

    float* sOut = reinterpret_cast<float*>(smem);
    const float* sMask = reinterpret_cast<const float*>(smem + P_MASK);
#pragma unroll
    for (int fm = 0; fm < 2; fm++)
#pragma unroll
        for (int fn = 0; fn < 2; fn++)
#pragma unroll
            for (int e = 0; e < 4; e++) {
                const int n_loc = wm * 32 + fm * 16 + (lane >> 2) + (e >> 1) * 8;
                const int o     = wn * 16 + fn * 8 + (lane & 3) * 2 + (e & 1);
                const float bias = (o < 32) ? ba[o] : bb[o - 32];
                sOut[o * 132 + n_loc] = (acc[fm][fn][e] + bias) * sMask[n_loc];
            }
    __syncthreads();

    {
        const int o  = tid >> 3;
        const int n0 = (tid & 7) * 16;
        __nv_bfloat16 hb[16], lb[16];
#pragma unroll
        for (int c = 0; c < 16; c++)
            split1(sOut[o * 132 + n0 + c], hb[c], lb[c]);
        __nv_bfloat16* dh = ((o < 32) ? g_Ah : g_Bh) + (size_t)(i * 32 + (o & 31)) * 128 + n0;
        __nv_bfloat16* dl = ((o < 32) ? g_Al : g_Bl) + (size_t)(i * 32 + (o & 31)) * 128 + n0;
        reinterpret_cast<uint4*>(dh)[0] = reinterpret_cast<const uint4*>(hb)[0];
        reinterpret_cast<uint4*>(dh)[1] = reinterpret_cast<const uint4*>(hb)[1];
        reinterpret_cast<uint4*>(dl)[0] = reinterpret_cast<const uint4*>(lb)[0];
        reinterpret_cast<uint4*>(dl)[1] = reinterpret_cast<const uint4*>(lb)[1];
    }
}

// ---------------------------------------------------------------------------
// Fused kernel: R13-exact (best measured). 256x128 tile (32 pairs).
// ---------------------------------------------------------------------------
#define F_AH   0
#define F_AL   69632
#define F_BH   139264
#define F_BL   174080
#define OFFO   65536
#define OFFOL  (OFFO + 66048)
#define OFFPM  197632
#define F_SMEM 208896

__global__ __launch_bounds__(512) void fused_kernel(
    const float* __restrict__ bo, float* __restrict__ out)
{
    extern __shared__ char smem[];
    const uint32_t sb = smem_u32(smem);
    const int tid  = threadIdx.x;
    const int lane = tid & 31;
    const int wid  = tid >> 5;
    const int bm = blockIdx.y, bn = blockIdx.x;   // bm 0..31, bn 0..63
    const int i0 = bm * 8, j0 = bn * 4;

    // ======================= Phase A ===============================
#pragma unroll
    for (int kh = 0; kh < 2; kh++) {
#pragma unroll
        for (int v = 0; v < 12; v++) {
            const int idx = v * 512 + tid;
            if (idx < 4096) {
                const int buf = idx >> 11;
                const int rem = idx & 2047;
                const int row = rem >> 3, q = rem & 7;
                const __nv_bfloat16* src = (buf ? g_Al : g_Ah) +
                    (size_t)(bm * 256 + row) * 128 + kh * 64 + q * 8;
                CP16(sb + (buf ? F_AL : F_AH) + row * 272 + kh * 128 + q * 16, src);
            } else {
                const int r2  = idx - 4096;
                const int buf = r2 >> 10;
                const int rem = r2 & 1023;
                const int row = rem >> 3, q = rem & 7;
                const __nv_bfloat16* src = (buf ? g_Bl : g_Bh) +
                    (size_t)(bn * 128 + row) * 128 + kh * 64 + q * 8;
                CP16(sb + (buf ? F_BL : F_BH) + row * 272 + kh * 128 + q * 16, src);
            }
        }
        CP_COMMIT();
    }

    const int wm = wid >> 1, wn = wid & 1;
    float acc[2][8][4];
#pragma unroll
    for (int fm = 0; fm < 2; fm++)
#pragma unroll
        for (int fn = 0; fn < 8; fn++)
#pragma unroll
            for (int e = 0; e < 4; e++) acc[fm][fn][e] = 0.f;

    const uint32_t rofsA = (uint32_t)((lane & 15) * 272 + (lane >> 4) * 16);
    const uint32_t aAh = sb + F_AH + wm * 32 * 272 + rofsA;
    const uint32_t aAl = sb + F_AL + wm * 32 * 272 + rofsA;
    const uint32_t aBh = sb + F_BH + wn * 64 * 272 + rofsA;
    const uint32_t aBl = sb + F_BL + wn * 64 * 272 + rofsA;

    CP_WAIT(1);
    __syncthreads();

#pragma unroll
    for (int ks = 0; ks < 8; ks++) {
        if (ks == 4) { CP_WAIT(0); __syncthreads(); }
        uint32_t A_h[2][4], A_l[2][4];
        ldsm4(A_h[0], aAh + ks * 32);
        ldsm4(A_h[1], aAh + 16 * 272 + ks * 32);
        ldsm4(A_l[0], aAl + ks * 32);
        ldsm4(A_l[1], aAl + 16 * 272 + ks * 32);
#pragma unroll
        for (int bh2 = 0; bh2 < 2; bh2++) {
            uint32_t B_h[2][4], B_l[2][4];
            const uint32_t bo0 = (uint32_t)(bh2 * 32 * 272 + ks * 32);
            ldsm4(B_h[0], aBh + bo0);
            ldsm4(B_h[1], aBh + 16 * 272 + bo0);
            ldsm4(B_l[0], aBl + bo0);
            ldsm4(B_l[1], aBl + 16 * 272 + bo0);
#pragma unroll
            for (int fm = 0; fm < 2; fm++)
#pragma unroll
                for (int fl = 0; fl < 4; fl++) {
                    const int fn = bh2 * 4 + fl;
                    const uint32_t bh0 = B_h[fl >> 1][fl & 1];
                    const uint32_t bh1 = B_h[fl >> 1][(fl & 1) + 2];
                    const uint32_t bl0 = B_l[fl >> 1][fl & 1];
                    const uint32_t bl1 = B_l[fl >> 1][(fl & 1) + 2];
                    mma_bf16(acc[fm][fn], A_h[fm], bh0, bh1);
                    mma_bf16(acc[fm][fn], A_h[fm], bl0, bl1);
                    mma_bf16(acc[fm][fn], A_l[fm], bh0, bh1);
                }
        }
    }

    __syncthreads();   // all A/B smem reads done; stage region reusable

    // ---- hoisted Wo streaming state ----
    const int wn2 = wid & 3;
    const int kc  = wid >> 2;
    const uint32_t wstage0 = sb + wid * 2048;
    const int rv = lane >> 1, hv = lane & 1;
    const uint32_t hsv = (uint32_t)((hv ^ ((rv >> 2) & 1)) << 4);
    const __nv_bfloat16* wsrc0 = g_Woh + (size_t)(wn2 * 32 + rv) * 1024 + kc * 16 + hv * 8;
    const __nv_bfloat16* wsrc1 = g_Woh + (size_t)(wn2 * 32 + 16 + rv) * 1024 + kc * 16 + hv * 8;
    const __nv_bfloat16* wsrc2 = g_Wol + (size_t)(wn2 * 32 + rv) * 1024 + kc * 16 + hv * 8;
    const __nv_bfloat16* wsrc3 = g_Wol + (size_t)(wn2 * 32 + 16 + rv) * 1024 + kc * 16 + hv * 8;
    const uint32_t d0 = (uint32_t)(rv * 32) + hsv;
    const uint32_t d1 = (uint32_t)((16 + rv) * 32) + hsv;

    // prologue: stream chunks 0 (stage 0) and 1 (stage 1)
#pragma unroll
    for (int pre = 0; pre < 2; pre++) {
        const uint32_t stb = wstage0 + pre * 32768;
        CP16(stb + d0, wsrc0);
        CP16(stb + d1, wsrc1);
        CP16(stb + 1024 + d0, wsrc2);
        CP16(stb + 1024 + d1, wsrc3);
        CP_COMMIT();
        wsrc0 += 64; wsrc1 += 64; wsrc2 += 64; wsrc3 += 64;
    }

    // ---- O spill: pair p = wm*4 + wn*2 + (fn>>2), k = c*32 + d ----
#pragma unroll
    for (int fm = 0; fm < 2; fm++)
#pragma unroll
        for (int fn = 0; fn < 8; fn++) {
            const int p = wm * 4 + wn * 2 + (fn >> 2);
            char* oh = smem + OFFO  + p * 2064;
            char* ol = smem + OFFOL + p * 2064;
#pragma unroll
            for (int half = 0; half < 2; half++) {
                const int c = fm * 16 + (lane >> 2) + half * 8;
                const int d = (fn & 3) * 8 + (lane & 3) * 2;
                const int k = c * 32 + d;
                __nv_bfloat162 h2, l2;
                split1(acc[fm][fn][half * 2 + 0], h2.x, l2.x);
                split1(acc[fm][fn][half * 2 + 1], h2.y, l2.y);
                *reinterpret_cast<__nv_bfloat162*>(oh + 2 * k) = h2;
                *reinterpret_cast<__nv_bfloat162*>(ol + 2 * k) = l2;
            }
        }
    if (tid < 32) {
        const int ii = i0 + (tid >> 2), jj = j0 + (tid & 3);
        *reinterpret_cast<float*>(smem + OFFPM + tid * 4) =
            1.f / (g_pm[ii * LL + jj] + 1e-8f);
    }
    __syncthreads();   // O + pm visible to all warps

    // ======================= Phase B: barrier-free, unrolled ================
    float acc2[2][4][4];
#pragma unroll
    for (int fm = 0; fm < 2; fm++)
#pragma unroll
        for (int fn = 0; fn < 4; fn++)
#pragma unroll
            for (int e = 0; e < 4; e++) acc2[fm][fn][e] = 0.f;

    const uint32_t aOh = sb + OFFO + (uint32_t)((lane & 15) * 2064 + (lane >> 4) * 16);
    const uint32_t aOl = aOh + 66048;
    const int rB  = lane & 15;
    const int cbB = lane >> 4;
    const uint32_t bofs = (uint32_t)(rB * 32 + ((cbB ^ ((rB >> 2) & 1)) << 4));

    // A fragments double-buffered in registers
    uint32_t AH[2][2][4], AL[2][2][4];
    {
        const uint32_t ao = (uint32_t)(kc * 32);
        ldsm4(AH[0][0], aOh + ao);
        ldsm4(AH[0][1], aOh + 16 * 2064 + ao);
        ldsm4(AL[0][0], aOl + ao);
        ldsm4(AL[0][1], aOl + 16 * 2064 + ao);
    }

#pragma unroll
    for (int ck = 0; ck < 16; ck++) {
        const int pp = ck & 1;
        if (ck < 15) {   // prefetch A frags for ck+1 (independent of cp.async)
            const uint32_t ao = (uint32_t)((ck + 1) * 128 + kc * 32);
            ldsm4(AH[pp ^ 1][0], aOh + ao);
            ldsm4(AH[pp ^ 1][1], aOh + 16 * 2064 + ao);
            ldsm4(AL[pp ^ 1][0], aOl + ao);
            ldsm4(AL[pp ^ 1][1], aOl + 16 * 2064 + ao);
        }
        if (ck == 15) CP_WAIT(0); else CP_WAIT(1);
        __syncwarp();

        uint32_t B_h[2][4], B_l[2][4];
        const uint32_t wb = wstage0 + pp * 32768;
        ldsm4(B_h[0], wb + bofs);
        ldsm4(B_h[1], wb + 512 + bofs);
        ldsm4(B_l[0], wb + 1024 + bofs);
        ldsm4(B_l[1], wb + 1536 + bofs);

        if (ck + 2 < 16) {   // stream chunk ck+2 into stage pp
            CP16(wb + d0, wsrc0);
            CP16(wb + d1, wsrc1);
            CP16(wb + 1024 + d0, wsrc2);
            CP16(wb + 1024 + d1, wsrc3);
            CP_COMMIT();
            wsrc0 += 64; wsrc1 += 64; wsrc2 += 64; wsrc3 += 64;
        }

#pragma unroll
        for (int fm = 0; fm < 2; fm++)
#pragma unroll
            for (int fn = 0; fn < 4; fn++) {
                const uint32_t bh0 = B_h[fn >> 1][fn & 1];
                const uint32_t bh1 = B_h[fn >> 1][(fn & 1) + 2];
                const uint32_t bl0 = B_l[fn >> 1][fn & 1];
                const uint32_t bl1 = B_l[fn >> 1][(fn & 1) + 2];
                mma_bf16(acc2[fm][fn], AH[pp][fm], bh0, bh1);
                mma_bf16(acc2[fm][fn], AH[pp][fm], bl0, bl1);
                mma_bf16(acc2[fm][fn], AL[pp][fm], bh0, bh1);
            }
    }

    // all warps must finish reading stage buffers before reduction reuses them
    __syncthreads();

    // ---- k-split reduction via smem [0, 49152) ----
    float* red = reinterpret_cast<float*>(smem);
    if (kc > 0) {
#pragma unroll
        for (int fm = 0; fm < 2; fm++)
#pragma unroll
            for (int fn = 0; fn < 4; fn++)
#pragma unroll
                for (int e = 0; e < 4; e++) {
                    const int p = fm * 16 + (lane >> 2) + (e >> 1) * 8;
                    const int z = wn2 * 32 + fn * 8 + (lane & 3) * 2 + (e & 1);
                    red[(kc - 1) * 4096 + p * 128 + z] = acc2[fm][fn][e];
                }
    }
    __syncthreads();
    if (kc == 0) {
        const float* pmv = reinterpret_cast<const float*>(smem + OFFPM);
#pragma unroll
        for (int fm = 0; fm < 2; fm++)
#pragma unroll
            for (int fn = 0; fn < 4; fn++)
#pragma unroll
                for (int e = 0; e < 4; e++) {
                    const int p = fm * 16 + (lane >> 2) + (e >> 1) * 8;
                    const int z = wn2 * 32 + fn * 8 + (lane & 3) * 2 + (e & 1);
                    acc2[fm][fn][e] += red[p * 128 + z]
                                     + red[4096 + p * 128 + z]
                                     + red[8192 + p * 128 + z];
                }
#pragma unroll
        for (int fm = 0; fm < 2; fm++)
#pragma unroll
            for (int fn = 0; fn < 4; fn++)
#pragma unroll
                for (int prow = 0; prow < 2; prow++) {
                    const int p  = fm * 16 + (lane >> 2) + prow * 8;
                    const int ii = i0 + (p >> 2), jj = j0 + (p & 3);
                    const float inv = pmv[p];
                    const int z = wn2 * 32 + fn * 8 + (lane & 3) * 2;
                    float2 res;
                    res.x = acc2[fm][fn][prow * 2 + 0] * inv + bo[z];
                    res.y = acc2[fm][fn][prow * 2 + 1] * inv + bo[z + 1];
                    *reinterpret_cast<float2*>(out + (size_t)(ii * LL + jj) * CZ + z) = res;
                }
    }
}

// ---------------------------------------------------------------------------
extern "C" void kernel_launch(void* const* d_in, const int* in_sizes, int n_in,
                              void* d_out, int out_size)
{
    const float* m     = (const float*)d_in[0];
    const float* mask  = (const float*)d_in[1];
    const float* gamma = (const float*)d_in[2];
    const float* beta  = (const float*)d_in[3];
    const float* Wa    = (const float*)d_in[4];
    const float* ba    = (const float*)d_in[5];
    const float* Wb    = (const float*)d_in[6];
    const float* bb    = (const float*)d_in[7];
    const float* Wo    = (const float*)d_in[8];
    const float* bo    = (const float*)d_in[9];
    float* out = (float*)d_out;

    cudaFuncSetAttribute(proj_kernel,  cudaFuncAttributeMaxDynamicSharedMemorySize, P_SMEM);
    cudaFuncSetAttribute(fused_kernel, cudaFuncAttributeMaxDynamicSharedMemorySize, F_SMEM);

    prep_kernel<<<384, 256>>>(mask, Wo, Wa, Wb);
    proj_kernel<<<256, 512, P_SMEM>>>(m, gamma, beta, mask, ba, bb);
    fused_kernel<<<dim3(64, 32), 512, F_SMEM>>>(bo, out);
}